// round 5
// baseline (speedup 1.0000x reference)
#include <cuda_runtime.h>
#include <cstdint>

// Problem constants
#define BATCH   16
#define TLEN    4096
#define KW      15
#define PAD     7

// Tiling
#define TT      512     // time tile per CTA
#define TTH     16      // t positions per thread (8 packed adjacent pairs)
#define NTHREADS 256    // 8 oc * 32 t-subtiles
#define XP      (TT/2 + 8)   // pair-row length (needs TT/2+7, 264 keeps 16B align)

typedef unsigned long long u64;

// ---------------------------------------------------------------------------
// Intermediate activation buffers (static device globals; no runtime alloc)
// ---------------------------------------------------------------------------
__device__ float g_h1[(size_t)BATCH * 512 * TLEN];  // leaf out   128 MiB
__device__ float g_h2[(size_t)BATCH * 256 * TLEN];  // int0 out    64 MiB
__device__ float g_h3[(size_t)BATCH * 256 * TLEN];  // br out      64 MiB
__device__ float g_h4[(size_t)BATCH * 128 * TLEN];  // int1 out    32 MiB
__device__ float g_h5[(size_t)BATCH *  64 * TLEN];  // int2 out    16 MiB
__device__ float g_h6[(size_t)BATCH *  32 * TLEN];  // int3 out     8 MiB
__device__ float g_h7[(size_t)BATCH *  16 * TLEN];  // int4 out     4 MiB

// ---------------------------------------------------------------------------
// Packed f32x2 helpers (FFMA2 only reachable via PTX)
// ---------------------------------------------------------------------------
__device__ __forceinline__ u64 pack2(float lo, float hi) {
    u64 r; asm("mov.b64 %0,{%1,%2};" : "=l"(r) : "f"(lo), "f"(hi)); return r;
}
__device__ __forceinline__ void unpack2(u64 v, float& lo, float& hi) {
    asm("mov.b64 {%0,%1},%2;" : "=f"(lo), "=f"(hi) : "l"(v));
}
__device__ __forceinline__ u64 ffma2(u64 a, u64 b, u64 c) {
    u64 d; asm("fma.rn.f32x2 %0,%1,%2,%3;" : "=l"(d) : "l"(a), "l"(b), "l"(c));
    return d;
}

// ---------------------------------------------------------------------------
// Grouped conv1d, K=15, SAME padding.
// Input staged ONCE (full CIN) in two pre-packed f32x2 alignments:
//   E[ci][i] = (X[2i],   X[2i+1])   /  O[ci][i] = (X[2i+1], X[2i+2])
// X[tl] = x[t0 + tl - 7].  Tap k=2j   : acc[a] += wE[j] * E[basep+a+j]
//                          Tap k=2j+1 : acc[a] += wO[j] * O[basep+a+j]
// Hot loop: LDS.128 only (windows as ulonglong2, weights padded to 16/chan,
// oc row stride CIN*16+2 u64 -> 8 oc rows on distinct banks), plus FFMA2.
// 144 issue slots per channel per warp, 120 of them FFMA2.
//
// Grid: (TLEN/TT, groups, BATCH). Block: 256 = 8 oc * 32 t-subtiles. 2 CTAs/SM.
// ---------------------------------------------------------------------------
template<int CIN, int C0, int COUT, bool ACT>
__global__ __launch_bounds__(NTHREADS, 2)
void gconv_kernel(const float* __restrict__ in0, long long bs0,
                  const float* __restrict__ in1, long long bs1,
                  const float* __restrict__ W,
                  const float* __restrict__ bias,
                  float* __restrict__ out, int G)
{
    extern __shared__ char smem_raw[];
    const int WROW2 = CIN * 16 + 2;         // u64 stride per oc row (16B-aligned,
                                            // +2 spreads oc rows across banks)
    u64*   sw2 = (u64*)smem_raw;            // COUT * WROW2
    u64*   sE  = sw2 + COUT * WROW2;        // CIN * XP   (even stays 16B-aligned)
    u64*   sO  = sE + CIN * XP;             // CIN * XP
    float* sb  = (float*)(sO + CIN * XP);

    const int b   = blockIdx.z;
    const int g   = blockIdx.y;
    const int t0  = blockIdx.x * TT;
    const int tid = threadIdx.x;

    // ---- stage packed (w,w) weights, padded layout [oc][ci*16 + k], k15 = 0 ----
    {
        const float* wsrc = W + (long long)g * COUT * CIN * KW;
        for (int i = tid; i < COUT * CIN * 16; i += NTHREADS) {
            int oc = i / (CIN * 16);
            int r  = i - oc * (CIN * 16);
            int ci = r >> 4;
            int k  = r & 15;
            float w = (k < 15) ? wsrc[(oc * CIN + ci) * KW + k] : 0.0f;
            sw2[oc * WROW2 + r] = pack2(w, w);
        }
        if (tid < COUT) sb[tid] = bias[g * COUT + tid];
    }

    // ---- stage input pairs in both alignments (full CIN, once) ----
    for (int idx = tid; idx < CIN * XP; idx += NTHREADS) {
        int ci = idx / XP;
        int i  = idx - ci * XP;
        const float* src;
        if (C0 == CIN || ci < C0)
            src = in0 + (long long)b * bs0 + (long long)(g * C0 + ci) * TLEN;
        else
            src = in1 + (long long)b * bs1 + (long long)(g * (CIN - C0) + (ci - C0)) * TLEN;
        int tA = t0 + 2 * i - PAD;          // X[2i]
        float v0 = (tA     >= 0 && tA     < TLEN) ? src[tA]     : 0.0f;
        float v1 = (tA + 1 >= 0 && tA + 1 < TLEN) ? src[tA + 1] : 0.0f;
        float v2 = (tA + 2 >= 0 && tA + 2 < TLEN) ? src[tA + 2] : 0.0f;
        sE[idx] = pack2(v0, v1);
        sO[idx] = pack2(v1, v2);
    }
    __syncthreads();

    // ---- compute ----
    const int oc    = tid & (COUT - 1);     // oc lane-minor
    const int tt    = tid >> 3;             // 0..31
    const int basep = tt * (TTH / 2);       // first output pair index (even)

    u64 acc[8];
#pragma unroll
    for (int j = 0; j < 8; j++) acc[j] = 0ull;

    const u64* wrow = sw2 + oc * WROW2;

#pragma unroll 1
    for (int ci = 0; ci < CIN; ci++) {
        const ulonglong2* ep = (const ulonglong2*)(sE + ci * XP + basep);
        const ulonglong2* op = (const ulonglong2*)(sO + ci * XP + basep);
        u64 e[16], o[16];
#pragma unroll
        for (int i = 0; i < 8; i++) { ulonglong2 v = ep[i]; e[2*i] = v.x; e[2*i+1] = v.y; }
#pragma unroll
        for (int i = 0; i < 8; i++) { ulonglong2 v = op[i]; o[2*i] = v.x; o[2*i+1] = v.y; }

        const ulonglong2* wp = (const ulonglong2*)(wrow + ci * 16);
#pragma unroll
        for (int j = 0; j < 8; j++) {
            ulonglong2 wv = wp[j];              // (w[2j], w[2j+1]); w[15] = 0 pad
#pragma unroll
            for (int a = 0; a < 8; a++) acc[a] = ffma2(e[j + a], wv.x, acc[a]);
            if (j < 7) {
#pragma unroll
                for (int a = 0; a < 8; a++) acc[a] = ffma2(o[j + a], wv.y, acc[a]);
            }
        }
    }

    // ---- epilogue: bias + leaky relu, vectorized store ----
    const float bv = sb[oc];
    float res[TTH];
#pragma unroll
    for (int j = 0; j < 8; j++) {
        float lo, hi;
        unpack2(acc[j], lo, hi);
        lo += bv; hi += bv;
        if (ACT) { lo = lo > 0.0f ? lo : 0.01f * lo; hi = hi > 0.0f ? hi : 0.01f * hi; }
        res[2 * j] = lo; res[2 * j + 1] = hi;
    }
    float* dst = out + (((long long)b * G + g) * COUT + oc) * TLEN + t0 + tt * TTH;
#pragma unroll
    for (int j = 0; j < 4; j++)
        ((float4*)dst)[j] = make_float4(res[4*j], res[4*j+1], res[4*j+2], res[4*j+3]);
}

// ---------------------------------------------------------------------------
// Root: 1x1 conv over 16 channels -> 1 channel (no activation)
// ---------------------------------------------------------------------------
__global__ void root_kernel(const float* __restrict__ h,
                            const float* __restrict__ w,
                            const float* __restrict__ bias,
                            float* __restrict__ out)
{
    int idx = blockIdx.x * blockDim.x + threadIdx.x;   // over BATCH*TLEN
    if (idx >= BATCH * TLEN) return;
    int b = idx / TLEN;
    int t = idx - b * TLEN;
    const float* hp = h + (long long)b * 16 * TLEN + t;
    float s = bias[0];
#pragma unroll
    for (int c = 0; c < 16; c++)
        s = fmaf(__ldg(&w[c]), hp[(long long)c * TLEN], s);
    out[idx] = s;
}

// ---------------------------------------------------------------------------
// Launch
// ---------------------------------------------------------------------------
static inline int smem_bytes(int cin, int cout) {
    return cout * (cin * 16 + 2) * 8      // padded packed weights
         + cin * XP * 8 * 2               // E + O (full CIN)
         + cout * 4;                      // bias
}

extern "C" void kernel_launch(void* const* d_in, const int* in_sizes, int n_in,
                              void* d_out, int out_size)
{
    const float* x      = (const float*)d_in[0];
    const float* W_leaf = (const float*)d_in[1];
    const float* b_leaf = (const float*)d_in[2];
    const float* W_int0 = (const float*)d_in[3];
    const float* b_int0 = (const float*)d_in[4];
    const float* W_br   = (const float*)d_in[5];
    const float* b_br   = (const float*)d_in[6];
    const float* W_int1 = (const float*)d_in[7];
    const float* b_int1 = (const float*)d_in[8];
    const float* W_int2 = (const float*)d_in[9];
    const float* b_int2 = (const float*)d_in[10];
    const float* W_int3 = (const float*)d_in[11];
    const float* b_int3 = (const float*)d_in[12];
    const float* W_int4 = (const float*)d_in[13];
    const float* b_int4 = (const float*)d_in[14];
    const float* W_root = (const float*)d_in[15];
    const float* b_root = (const float*)d_in[16];
    float* out = (float*)d_out;

    float *h1, *h2, *h3, *h4, *h5, *h6, *h7;
    cudaGetSymbolAddress((void**)&h1, g_h1);
    cudaGetSymbolAddress((void**)&h2, g_h2);
    cudaGetSymbolAddress((void**)&h3, g_h3);
    cudaGetSymbolAddress((void**)&h4, g_h4);
    cudaGetSymbolAddress((void**)&h5, g_h5);
    cudaGetSymbolAddress((void**)&h6, g_h6);
    cudaGetSymbolAddress((void**)&h7, g_h7);

    const int TB = TLEN / TT;   // 8 tiles along T
    const long long BSX = (long long)1536 * TLEN;

    const int SM20 = smem_bytes(20, 8);   // ~105 KB  (2 CTAs = 210 KB <= 228)
    const int SM16 = smem_bytes(16, 8);   // ~84 KB   (2 CTAs = 168 KB)

    cudaFuncSetAttribute(gconv_kernel<20, 20, 8, true>,
                         cudaFuncAttributeMaxDynamicSharedMemorySize, SM20);
    cudaFuncSetAttribute(gconv_kernel<16, 16, 8, true>,
                         cudaFuncAttributeMaxDynamicSharedMemorySize, SM16);
    cudaFuncSetAttribute(gconv_kernel<16, 8, 8, true>,
                         cudaFuncAttributeMaxDynamicSharedMemorySize, SM16);

    // 1. leaf: 64 groups, 20 in/group, 8 out/group
    gconv_kernel<20, 20, 8, true><<<dim3(TB, 64, BATCH), NTHREADS, SM20>>>(
        x, BSX, nullptr, 0, W_leaf, b_leaf, h1, 64);

    // 2. int0: 32 groups, 16 in/group (from 512 ch)
    gconv_kernel<16, 16, 8, true><<<dim3(TB, 32, BATCH), NTHREADS, SM16>>>(
        h1, (long long)512 * TLEN, nullptr, 0, W_int0, b_int0, h2, 32);

    // 3. br: 32 groups, in/group = 8 (h2) + 8 (syn = x channels 1280..1535)
    gconv_kernel<16, 8, 8, true><<<dim3(TB, 32, BATCH), NTHREADS, SM16>>>(
        h2, (long long)256 * TLEN,
        x + (long long)1280 * TLEN, BSX,
        W_br, b_br, h3, 32);

    // 4. int1: 16 groups (256 -> 128)
    gconv_kernel<16, 16, 8, true><<<dim3(TB, 16, BATCH), NTHREADS, SM16>>>(
        h3, (long long)256 * TLEN, nullptr, 0, W_int1, b_int1, h4, 16);

    // 5. int2: 8 groups (128 -> 64)
    gconv_kernel<16, 16, 8, true><<<dim3(TB, 8, BATCH), NTHREADS, SM16>>>(
        h4, (long long)128 * TLEN, nullptr, 0, W_int2, b_int2, h5, 8);

    // 6. int3: 4 groups (64 -> 32)
    gconv_kernel<16, 16, 8, true><<<dim3(TB, 4, BATCH), NTHREADS, SM16>>>(
        h5, (long long)64 * TLEN, nullptr, 0, W_int3, b_int3, h6, 4);

    // 7. int4: 2 groups (32 -> 16)
    gconv_kernel<16, 16, 8, true><<<dim3(TB, 2, BATCH), NTHREADS, SM16>>>(
        h6, (long long)32 * TLEN, nullptr, 0, W_int4, b_int4, h7, 2);

    // 8. root: 1x1 conv 16 -> 1
    root_kernel<<<(BATCH * TLEN + 255) / 256, 256>>>(h7, W_root, b_root, out);
}

// round 6
// speedup vs baseline: 1.0224x; 1.0224x over previous
#include <cuda_runtime.h>
#include <cstdint>

// Problem constants
#define BATCH   16
#define TLEN    4096
#define KW      15
#define PAD     7

// Tiling
#define TT      256     // time tile per CTA
#define TTH     8       // t positions per thread (4 packed adjacent pairs)
#define NTHREADS 256    // 8 oc * 32 t-subtiles
#define XP      (TT/2 + 8)   // pair-row length = 136 (needs TT/2+7; even -> 16B rows)

typedef unsigned long long u64;

// ---------------------------------------------------------------------------
// Intermediate activation buffers (static device globals; no runtime alloc)
// ---------------------------------------------------------------------------
__device__ float g_h1[(size_t)BATCH * 512 * TLEN];  // leaf out   128 MiB
__device__ float g_h2[(size_t)BATCH * 256 * TLEN];  // int0 out    64 MiB
__device__ float g_h3[(size_t)BATCH * 256 * TLEN];  // br out      64 MiB
__device__ float g_h4[(size_t)BATCH * 128 * TLEN];  // int1 out    32 MiB
__device__ float g_h5[(size_t)BATCH *  64 * TLEN];  // int2 out    16 MiB
__device__ float g_h6[(size_t)BATCH *  32 * TLEN];  // int3 out     8 MiB
__device__ float g_h7[(size_t)BATCH *  16 * TLEN];  // int4 out     4 MiB

// ---------------------------------------------------------------------------
// Packed f32x2 helpers (FFMA2 only reachable via PTX)
// ---------------------------------------------------------------------------
__device__ __forceinline__ u64 pack2(float lo, float hi) {
    u64 r; asm("mov.b64 %0,{%1,%2};" : "=l"(r) : "f"(lo), "f"(hi)); return r;
}
__device__ __forceinline__ void unpack2(u64 v, float& lo, float& hi) {
    asm("mov.b64 {%0,%1},%2;" : "=f"(lo), "=f"(hi) : "l"(v));
}
__device__ __forceinline__ u64 ffma2(u64 a, u64 b, u64 c) {
    u64 d; asm("fma.rn.f32x2 %0,%1,%2,%3;" : "=l"(d) : "l"(a), "l"(b), "l"(c));
    return d;
}

// ---------------------------------------------------------------------------
// Grouped conv1d, K=15, SAME padding, occupancy-first design (4 CTAs/SM).
// Input staged per-CHUNK in two pre-packed f32x2 alignments:
//   E[ci][i] = (X[2i],   X[2i+1])   /  O[ci][i] = (X[2i+1], X[2i+2])
// X[tl] = x[t0 + tl - 7].
// Weights SOA-packed per channel: slot j<8 -> (w[2j],w[2j]); slot 8+j -> (w[2j+1],...).
// Per channel: [4x LDS.128 wE | 6x LDS.128 e | 32 FFMA2] then
//              [4x LDS.128 wO | 5x LDS.128 o | 28 FFMA2]  — small reg windows,
// short load bursts, all window loads conflict-free (4 subtiles span one 128B line).
//
// Grid: (TLEN/TT, groups, BATCH). Block: 256 = 8 oc * 32 t-subtiles.
// ---------------------------------------------------------------------------
template<int CIN, int C0, int COUT, int CHUNK, bool ACT>
__global__ __launch_bounds__(NTHREADS, 4)
void gconv_kernel(const float* __restrict__ in0, long long bs0,
                  const float* __restrict__ in1, long long bs1,
                  const float* __restrict__ W,
                  const float* __restrict__ bias,
                  float* __restrict__ out, int G)
{
    extern __shared__ char smem_raw[];
    const int WROW2 = CIN * 16 + 2;         // u64 stride per oc row (16B-aligned,
                                            // +2 spreads oc rows across banks)
    u64*   sw2 = (u64*)smem_raw;            // COUT * WROW2 (SOA wE|wO per channel)
    u64*   sE  = sw2 + COUT * WROW2;        // CHUNK * XP
    u64*   sO  = sE + CHUNK * XP;           // CHUNK * XP
    float* sb  = (float*)(sO + CHUNK * XP);

    const int b   = blockIdx.z;
    const int g   = blockIdx.y;
    const int t0  = blockIdx.x * TT;
    const int tid = threadIdx.x;

    // ---- stage SOA packed weights: [oc][ci*16 + s], s<8: w[2s]; s=8..14: w[2s-15]; s15=0
    {
        const float* wsrc = W + (long long)g * COUT * CIN * KW;
        for (int i = tid; i < COUT * CIN * 16; i += NTHREADS) {
            int oc = i / (CIN * 16);
            int r  = i - oc * (CIN * 16);
            int ci = r >> 4;
            int s  = r & 15;
            float w = 0.0f;
            if (s < 8)            w = wsrc[(oc * CIN + ci) * KW + 2 * s];      // even taps
            else if (s < 15)      w = wsrc[(oc * CIN + ci) * KW + 2 * (s - 8) + 1]; // odd
            sw2[oc * WROW2 + r] = pack2(w, w);
        }
        if (tid < COUT) sb[tid] = bias[g * COUT + tid];
    }

    const int oc    = tid & (COUT - 1);     // oc lane-minor
    const int tt    = tid >> 3;             // 0..31
    const int basep = tt * (TTH / 2);       // first output pair index (mult of 4)

    u64 acc[4];
#pragma unroll
    for (int j = 0; j < 4; j++) acc[j] = 0ull;

    const u64* wrow = sw2 + oc * WROW2;

    // ---- channel chunks: stage (STS.128) -> compute ----
#pragma unroll 1
    for (int c0 = 0; c0 < CIN; c0 += CHUNK) {
        __syncthreads();   // WAR: previous compute / weight staging done

        // stage CHUNK channels; each iteration fills 2 pair-slots with 16B stores
        for (int idx = tid; idx < CHUNK * (XP / 2); idx += NTHREADS) {
            int cl = idx / (XP / 2);
            int ii = idx - cl * (XP / 2);
            int i  = 2 * ii;                 // first pair slot
            int ci = c0 + cl;
            const float* src;
            if (C0 == CIN || ci < C0)
                src = in0 + (long long)b * bs0 + (long long)(g * C0 + ci) * TLEN;
            else
                src = in1 + (long long)b * bs1 + (long long)(g * (CIN - C0) + (ci - C0)) * TLEN;
            int tA = t0 + 2 * i - PAD;       // X[2i]
            float v0 = (tA     >= 0 && tA     < TLEN) ? src[tA]     : 0.0f;
            float v1 = (tA + 1 >= 0 && tA + 1 < TLEN) ? src[tA + 1] : 0.0f;
            float v2 = (tA + 2 >= 0 && tA + 2 < TLEN) ? src[tA + 2] : 0.0f;
            float v3 = (tA + 3 >= 0 && tA + 3 < TLEN) ? src[tA + 3] : 0.0f;
            float v4 = (tA + 4 >= 0 && tA + 4 < TLEN) ? src[tA + 4] : 0.0f;
            ulonglong2 ev; ev.x = pack2(v0, v1); ev.y = pack2(v2, v3);
            ulonglong2 ov; ov.x = pack2(v1, v2); ov.y = pack2(v3, v4);
            ((ulonglong2*)(sE + cl * XP))[ii] = ev;
            ((ulonglong2*)(sO + cl * XP))[ii] = ov;
        }
        __syncthreads();

#pragma unroll 1
        for (int cl = 0; cl < CHUNK; cl++) {
            const u64* wp = wrow + (c0 + cl) * 16;

            // ---- pass 1: even taps ----
            {
                ulonglong2 wv0 = ((const ulonglong2*)wp)[0];
                ulonglong2 wv1 = ((const ulonglong2*)wp)[1];
                ulonglong2 wv2 = ((const ulonglong2*)wp)[2];
                ulonglong2 wv3 = ((const ulonglong2*)wp)[3];
                u64 e[12];
                const ulonglong2* ep = (const ulonglong2*)(sE + cl * XP + basep);
#pragma unroll
                for (int i = 0; i < 6; i++) { ulonglong2 v = ep[i]; e[2*i] = v.x; e[2*i+1] = v.y; }
                u64 w;
                w = wv0.x;
#pragma unroll
                for (int a = 0; a < 4; a++) acc[a] = ffma2(e[a + 0], w, acc[a]);
                w = wv0.y;
#pragma unroll
                for (int a = 0; a < 4; a++) acc[a] = ffma2(e[a + 1], w, acc[a]);
                w = wv1.x;
#pragma unroll
                for (int a = 0; a < 4; a++) acc[a] = ffma2(e[a + 2], w, acc[a]);
                w = wv1.y;
#pragma unroll
                for (int a = 0; a < 4; a++) acc[a] = ffma2(e[a + 3], w, acc[a]);
                w = wv2.x;
#pragma unroll
                for (int a = 0; a < 4; a++) acc[a] = ffma2(e[a + 4], w, acc[a]);
                w = wv2.y;
#pragma unroll
                for (int a = 0; a < 4; a++) acc[a] = ffma2(e[a + 5], w, acc[a]);
                w = wv3.x;
#pragma unroll
                for (int a = 0; a < 4; a++) acc[a] = ffma2(e[a + 6], w, acc[a]);
                w = wv3.y;
#pragma unroll
                for (int a = 0; a < 4; a++) acc[a] = ffma2(e[a + 7], w, acc[a]);
            }
            // ---- pass 2: odd taps ----
            {
                ulonglong2 wv0 = ((const ulonglong2*)wp)[4];
                ulonglong2 wv1 = ((const ulonglong2*)wp)[5];
                ulonglong2 wv2 = ((const ulonglong2*)wp)[6];
                u64 wlast = wp[14];
                u64 o[10];
                const ulonglong2* op = (const ulonglong2*)(sO + cl * XP + basep);
#pragma unroll
                for (int i = 0; i < 5; i++) { ulonglong2 v = op[i]; o[2*i] = v.x; o[2*i+1] = v.y; }
                u64 w;
                w = wv0.x;
#pragma unroll
                for (int a = 0; a < 4; a++) acc[a] = ffma2(o[a + 0], w, acc[a]);
                w = wv0.y;
#pragma unroll
                for (int a = 0; a < 4; a++) acc[a] = ffma2(o[a + 1], w, acc[a]);
                w = wv1.x;
#pragma unroll
                for (int a = 0; a < 4; a++) acc[a] = ffma2(o[a + 2], w, acc[a]);
                w = wv1.y;
#pragma unroll
                for (int a = 0; a < 4; a++) acc[a] = ffma2(o[a + 3], w, acc[a]);
                w = wv2.x;
#pragma unroll
                for (int a = 0; a < 4; a++) acc[a] = ffma2(o[a + 4], w, acc[a]);
                w = wv2.y;
#pragma unroll
                for (int a = 0; a < 4; a++) acc[a] = ffma2(o[a + 5], w, acc[a]);
                w = wlast;
#pragma unroll
                for (int a = 0; a < 4; a++) acc[a] = ffma2(o[a + 6], w, acc[a]);
            }
        }
    }

    // ---- epilogue: bias + leaky relu, vectorized store ----
    const float bv = sb[oc];
    float res[TTH];
#pragma unroll
    for (int j = 0; j < 4; j++) {
        float lo, hi;
        unpack2(acc[j], lo, hi);
        lo += bv; hi += bv;
        if (ACT) { lo = lo > 0.0f ? lo : 0.01f * lo; hi = hi > 0.0f ? hi : 0.01f * hi; }
        res[2 * j] = lo; res[2 * j + 1] = hi;
    }
    float* dst = out + (((long long)b * G + g) * COUT + oc) * TLEN + t0 + tt * TTH;
#pragma unroll
    for (int j = 0; j < 2; j++)
        ((float4*)dst)[j] = make_float4(res[4*j], res[4*j+1], res[4*j+2], res[4*j+3]);
}

// ---------------------------------------------------------------------------
// Root: 1x1 conv over 16 channels -> 1 channel (no activation)
// ---------------------------------------------------------------------------
__global__ void root_kernel(const float* __restrict__ h,
                            const float* __restrict__ w,
                            const float* __restrict__ bias,
                            float* __restrict__ out)
{
    int idx = blockIdx.x * blockDim.x + threadIdx.x;   // over BATCH*TLEN
    if (idx >= BATCH * TLEN) return;
    int b = idx / TLEN;
    int t = idx - b * TLEN;
    const float* hp = h + (long long)b * 16 * TLEN + t;
    float s = bias[0];
#pragma unroll
    for (int c = 0; c < 16; c++)
        s = fmaf(__ldg(&w[c]), hp[(long long)c * TLEN], s);
    out[idx] = s;
}

// ---------------------------------------------------------------------------
// Launch
// ---------------------------------------------------------------------------
static inline int smem_bytes(int cin, int cout, int chunk) {
    return cout * (cin * 16 + 2) * 8      // SOA packed weights
         + chunk * XP * 8 * 2             // E + O chunk
         + cout * 4;                      // bias
}

extern "C" void kernel_launch(void* const* d_in, const int* in_sizes, int n_in,
                              void* d_out, int out_size)
{
    const float* x      = (const float*)d_in[0];
    const float* W_leaf = (const float*)d_in[1];
    const float* b_leaf = (const float*)d_in[2];
    const float* W_int0 = (const float*)d_in[3];
    const float* b_int0 = (const float*)d_in[4];
    const float* W_br   = (const float*)d_in[5];
    const float* b_br   = (const float*)d_in[6];
    const float* W_int1 = (const float*)d_in[7];
    const float* b_int1 = (const float*)d_in[8];
    const float* W_int2 = (const float*)d_in[9];
    const float* b_int2 = (const float*)d_in[10];
    const float* W_int3 = (const float*)d_in[11];
    const float* b_int3 = (const float*)d_in[12];
    const float* W_int4 = (const float*)d_in[13];
    const float* b_int4 = (const float*)d_in[14];
    const float* W_root = (const float*)d_in[15];
    const float* b_root = (const float*)d_in[16];
    float* out = (float*)d_out;

    float *h1, *h2, *h3, *h4, *h5, *h6, *h7;
    cudaGetSymbolAddress((void**)&h1, g_h1);
    cudaGetSymbolAddress((void**)&h2, g_h2);
    cudaGetSymbolAddress((void**)&h3, g_h3);
    cudaGetSymbolAddress((void**)&h4, g_h4);
    cudaGetSymbolAddress((void**)&h5, g_h5);
    cudaGetSymbolAddress((void**)&h6, g_h6);
    cudaGetSymbolAddress((void**)&h7, g_h7);

    const int TB = TLEN / TT;   // 16 tiles along T
    const long long BSX = (long long)1536 * TLEN;

    const int SM20 = smem_bytes(20, 8, 5);   // ~31.5 KB
    const int SM16 = smem_bytes(16, 8, 8);   // ~34 KB

    cudaFuncSetAttribute(gconv_kernel<20, 20, 8, 5, true>,
                         cudaFuncAttributeMaxDynamicSharedMemorySize, SM20);
    cudaFuncSetAttribute(gconv_kernel<16, 16, 8, 8, true>,
                         cudaFuncAttributeMaxDynamicSharedMemorySize, SM16);
    cudaFuncSetAttribute(gconv_kernel<16, 8, 8, 8, true>,
                         cudaFuncAttributeMaxDynamicSharedMemorySize, SM16);

    // 1. leaf: 64 groups, 20 in/group, 8 out/group (chunks of 5)
    gconv_kernel<20, 20, 8, 5, true><<<dim3(TB, 64, BATCH), NTHREADS, SM20>>>(
        x, BSX, nullptr, 0, W_leaf, b_leaf, h1, 64);

    // 2. int0: 32 groups, 16 in/group (from 512 ch)
    gconv_kernel<16, 16, 8, 8, true><<<dim3(TB, 32, BATCH), NTHREADS, SM16>>>(
        h1, (long long)512 * TLEN, nullptr, 0, W_int0, b_int0, h2, 32);

    // 3. br: 32 groups, in/group = 8 (h2) + 8 (syn = x channels 1280..1535)
    gconv_kernel<16, 8, 8, 8, true><<<dim3(TB, 32, BATCH), NTHREADS, SM16>>>(
        h2, (long long)256 * TLEN,
        x + (long long)1280 * TLEN, BSX,
        W_br, b_br, h3, 32);

    // 4. int1: 16 groups (256 -> 128)
    gconv_kernel<16, 16, 8, 8, true><<<dim3(TB, 16, BATCH), NTHREADS, SM16>>>(
        h3, (long long)256 * TLEN, nullptr, 0, W_int1, b_int1, h4, 16);

    // 5. int2: 8 groups (128 -> 64)
    gconv_kernel<16, 16, 8, 8, true><<<dim3(TB, 8, BATCH), NTHREADS, SM16>>>(
        h4, (long long)128 * TLEN, nullptr, 0, W_int2, b_int2, h5, 8);

    // 6. int3: 4 groups (64 -> 32)
    gconv_kernel<16, 16, 8, 8, true><<<dim3(TB, 4, BATCH), NTHREADS, SM16>>>(
        h5, (long long)64 * TLEN, nullptr, 0, W_int3, b_int3, h6, 4);

    // 7. int4: 2 groups (32 -> 16)
    gconv_kernel<16, 16, 8, 8, true><<<dim3(TB, 2, BATCH), NTHREADS, SM16>>>(
        h6, (long long)32 * TLEN, nullptr, 0, W_int4, b_int4, h7, 2);

    // 8. root: 1x1 conv 16 -> 1
    root_kernel<<<(BATCH * TLEN + 255) / 256, 256>>>(h7, W_root, b_root, out);
}

// round 7
// speedup vs baseline: 1.1797x; 1.1538x over previous
#include <cuda_runtime.h>
#include <cstdint>

// Problem constants
#define BATCH   16
#define TLEN    4096
#define KW      15

// Tiling
#define TT      512     // time tile per CTA
#define TTH     16      // t positions per thread (8 packed adjacent pairs)
#define NTHREADS 256    // 8 oc * 32 t-subtiles
#define XP      (TT/2 + 8)   // pair-row length (264)
#define CHUNKI  4       // channels per staged chunk

typedef unsigned long long u64;

// ---------------------------------------------------------------------------
// Intermediate activation buffers (static device globals; no runtime alloc)
// ---------------------------------------------------------------------------
__device__ float g_h1[(size_t)BATCH * 512 * TLEN];  // leaf out   128 MiB
__device__ float g_h2[(size_t)BATCH * 256 * TLEN];  // int0 out    64 MiB
__device__ float g_h3[(size_t)BATCH * 256 * TLEN];  // br out      64 MiB
__device__ float g_h4[(size_t)BATCH * 128 * TLEN];  // int1 out    32 MiB
__device__ float g_h5[(size_t)BATCH *  64 * TLEN];  // int2 out    16 MiB
__device__ float g_h6[(size_t)BATCH *  32 * TLEN];  // int3 out     8 MiB
__device__ float g_h7[(size_t)BATCH *  16 * TLEN];  // int4 out     4 MiB

// ---------------------------------------------------------------------------
// Packed f32x2 helpers (FFMA2 only reachable via PTX)
// ---------------------------------------------------------------------------
__device__ __forceinline__ u64 pack2(float lo, float hi) {
    u64 r; asm("mov.b64 %0,{%1,%2};" : "=l"(r) : "f"(lo), "f"(hi)); return r;
}
__device__ __forceinline__ void unpack2(u64 v, float& lo, float& hi) {
    asm("mov.b64 {%0,%1},%2;" : "=f"(lo), "=f"(hi) : "l"(v));
}
__device__ __forceinline__ u64 ffma2(u64 a, u64 b, u64 c) {
    u64 d; asm("fma.rn.f32x2 %0,%1,%2,%3;" : "=l"(d) : "l"(a), "l"(b), "l"(c));
    return d;
}
// cp.async with zfill: copies sz bytes (0 or full), zero-fills the rest
__device__ __forceinline__ void cpa8(uint32_t dst, const float* src, int sz) {
    asm volatile("cp.async.ca.shared.global [%0], [%1], 8, %2;\n"
                 :: "r"(dst), "l"(src), "r"(sz));
}
__device__ __forceinline__ void cpa4(uint32_t dst, const float* src, int sz) {
    asm volatile("cp.async.ca.shared.global [%0], [%1], 4, %2;\n"
                 :: "r"(dst), "l"(src), "r"(sz));
}
__device__ __forceinline__ void cpa_commit() {
    asm volatile("cp.async.commit_group;\n");
}
__device__ __forceinline__ void cpa_wait0() {
    asm volatile("cp.async.wait_group 0;\n");
}

// ---------------------------------------------------------------------------
// Grouped conv1d, K=15, SAME padding, cp.async double-buffered staging.
//
// Pair grid rebased at t0-8 so BOTH smem images are plain shifted copies of x:
//   E[i] = (x[t0-8+2i], x[t0-8+2i+1])   -> 8B cp.async (8B-aligned src)
//   O[i] = (x[t0-8+2i+1], x[t0-8+2i+2]) -> 2x 4B cp.async
// Output pair u=16tt+2a, tap k, m=k>>1:
//   k even: acc[a] += w2[k] * O[basep+a+m]
//   k odd : acc[a] += w2[k] * E[basep+a+m+1]
// Hot loop identical in structure to R4 (best known): 29 window LDS.64 +
// 15 weight LDS.64 + 120 FFMA2 per channel.  Staging of chunk c+1 overlaps
// compute of chunk c via cp.async groups; one __syncthreads per chunk.
//
// Grid: (TLEN/TT, groups, BATCH). Block: 256 = 8 oc * 32 t-subtiles. 3 CTAs/SM.
// Dyn smem: [ sw2: COUT*(CIN*KW+1) u64 | 2 x (E:CHUNK*XP | O:CHUNK*XP) u64 | sb ]
// ---------------------------------------------------------------------------
template<int CIN, int C0, int COUT, bool ACT>
__global__ __launch_bounds__(NTHREADS, 3)
void gconv_kernel(const float* __restrict__ in0, long long bs0,
                  const float* __restrict__ in1, long long bs1,
                  const float* __restrict__ W,
                  const float* __restrict__ bias,
                  float* __restrict__ out, int G)
{
    extern __shared__ char smem_raw[];
    const int WROW = CIN * KW + 1;          // odd u64 stride: oc rows spread banks
    u64*   sw2 = (u64*)smem_raw;            // packed (w,w) weights
    u64*   sEO = sw2 + COUT * WROW;         // 2 buffers x (E | O), CHUNKI*XP each
    float* sb  = (float*)(sEO + 2 * 2 * CHUNKI * XP);

    const int b   = blockIdx.z;
    const int g   = blockIdx.y;
    const int t0  = blockIdx.x * TT;
    const int tid = threadIdx.x;

    // ---- stage packed (w,w) weights for this group (plain path, once) ----
    {
        const float* wsrc = W + (long long)g * COUT * CIN * KW;
        for (int i = tid; i < COUT * CIN * KW; i += NTHREADS) {
            int oc = i / (CIN * KW);
            int r  = i - oc * (CIN * KW);
            float w = wsrc[i];
            sw2[oc * WROW + r] = pack2(w, w);
        }
        if (tid < COUT) sb[tid] = bias[g * COUT + tid];
    }

    // per-channel source row
    auto srcbase = [&](int ci) -> const float* {
        if (C0 == CIN || ci < C0)
            return in0 + (long long)b * bs0 + (long long)(g * C0 + ci) * TLEN;
        return in1 + (long long)b * bs1 + (long long)(g * (CIN - C0) + (ci - C0)) * TLEN;
    };

    // stage CHUNKI channels [c0, c0+CHUNKI) into buffer `buf` via cp.async
    auto stage = [&](int c0, int buf) {
        u64* sE = sEO + buf * (2 * CHUNKI * XP);
        u64* sO = sE + CHUNKI * XP;
        uint32_t aE = (uint32_t)__cvta_generic_to_shared(sE);
        uint32_t aO = (uint32_t)__cvta_generic_to_shared(sO);
        // E: 8B copies, element f = t0-8+2i (even -> 8B aligned, no straddle)
        for (int idx = tid; idx < CHUNKI * XP; idx += NTHREADS) {
            int cl = idx / XP, i = idx - cl * XP;
            const float* src = srcbase(c0 + cl);
            int f  = t0 - 8 + 2 * i;
            int sz = ((unsigned)f < (unsigned)(TLEN - 1)) ? 8 : 0;
            int fc = f < 0 ? 0 : (f > TLEN - 2 ? TLEN - 2 : f);
            cpa8(aE + (uint32_t)idx * 8, src + fc, sz);
        }
        // O: 4B copies, float r of row = x[t0-7+r]
        for (int idx = tid; idx < CHUNKI * 2 * XP; idx += NTHREADS) {
            int cl = idx / (2 * XP), r = idx - cl * 2 * XP;
            const float* src = srcbase(c0 + cl);
            int q  = t0 - 7 + r;
            int sz = ((unsigned)q < (unsigned)TLEN) ? 4 : 0;
            int qc = q < 0 ? 0 : (q > TLEN - 1 ? TLEN - 1 : q);
            cpa4(aO + (uint32_t)idx * 4, src + qc, sz);
        }
    };

    const int oc    = tid & (COUT - 1);     // oc lane-minor
    const int tt    = tid >> 3;             // 0..31
    const int basep = tt * (TTH / 2);       // first output pair index

    u64 acc[8];
#pragma unroll
    for (int j = 0; j < 8; j++) acc[j] = 0ull;

    const u64* wrow = sw2 + oc * WROW;

    // ---- prologue: stage chunk 0 ----
    stage(0, 0);
    cpa_commit();
    cpa_wait0();
    __syncthreads();                        // chunk0 + weights visible

    const int NCH = CIN / CHUNKI;
#pragma unroll 1
    for (int c = 0; c < NCH; c++) {
        const int cur = c & 1;
        if (c + 1 < NCH) stage((c + 1) * CHUNKI, cur ^ 1);
        cpa_commit();

        u64* sE = sEO + cur * (2 * CHUNKI * XP);
        u64* sO = sE + CHUNKI * XP;

#pragma unroll 1
        for (int cl = 0; cl < CHUNKI; cl++) {
            const u64* op = sO + cl * XP + basep;       // even taps
            const u64* ep = sE + cl * XP + basep + 1;   // odd taps
            u64 o[15], e[14];
#pragma unroll
            for (int i = 0; i < 15; i++) o[i] = op[i];
#pragma unroll
            for (int i = 0; i < 14; i++) e[i] = ep[i];

            const u64* wp = wrow + (c * CHUNKI + cl) * KW;
#pragma unroll
            for (int k = 0; k < KW; k++) {
                u64 w2 = wp[k];
                int m = k >> 1;
                if ((k & 1) == 0) {
#pragma unroll
                    for (int a = 0; a < 8; a++) acc[a] = ffma2(o[a + m], w2, acc[a]);
                } else {
#pragma unroll
                    for (int a = 0; a < 8; a++) acc[a] = ffma2(e[a + m], w2, acc[a]);
                }
            }
        }

        cpa_wait0();          // next chunk's data arrived (overlapped with compute)
        __syncthreads();      // all warps done with cur; safe to reuse next iter
    }

    // ---- epilogue: bias + leaky relu, vectorized store ----
    const float bv = sb[oc];
    float res[TTH];
#pragma unroll
    for (int j = 0; j < 8; j++) {
        float lo, hi;
        unpack2(acc[j], lo, hi);
        lo += bv; hi += bv;
        if (ACT) { lo = lo > 0.0f ? lo : 0.01f * lo; hi = hi > 0.0f ? hi : 0.01f * hi; }
        res[2 * j] = lo; res[2 * j + 1] = hi;
    }
    float* dst = out + (((long long)b * G + g) * COUT + oc) * TLEN + t0 + tt * TTH;
#pragma unroll
    for (int j = 0; j < 4; j++)
        ((float4*)dst)[j] = make_float4(res[4*j], res[4*j+1], res[4*j+2], res[4*j+3]);
}

// ---------------------------------------------------------------------------
// Root: 1x1 conv over 16 channels -> 1 channel (no activation)
// ---------------------------------------------------------------------------
__global__ void root_kernel(const float* __restrict__ h,
                            const float* __restrict__ w,
                            const float* __restrict__ bias,
                            float* __restrict__ out)
{
    int idx = blockIdx.x * blockDim.x + threadIdx.x;   // over BATCH*TLEN
    if (idx >= BATCH * TLEN) return;
    int b = idx / TLEN;
    int t = idx - b * TLEN;
    const float* hp = h + (long long)b * 16 * TLEN + t;
    float s = bias[0];
#pragma unroll
    for (int c = 0; c < 16; c++)
        s = fmaf(__ldg(&w[c]), hp[(long long)c * TLEN], s);
    out[idx] = s;
}

// ---------------------------------------------------------------------------
// Launch
// ---------------------------------------------------------------------------
static inline int smem_bytes(int cin, int cout) {
    return cout * (cin * KW + 1) * 8      // packed weights
         + 2 * 2 * CHUNKI * XP * 8        // double-buffered E + O
         + cout * 4;                      // bias
}

extern "C" void kernel_launch(void* const* d_in, const int* in_sizes, int n_in,
                              void* d_out, int out_size)
{
    const float* x      = (const float*)d_in[0];
    const float* W_leaf = (const float*)d_in[1];
    const float* b_leaf = (const float*)d_in[2];
    const float* W_int0 = (const float*)d_in[3];
    const float* b_int0 = (const float*)d_in[4];
    const float* W_br   = (const float*)d_in[5];
    const float* b_br   = (const float*)d_in[6];
    const float* W_int1 = (const float*)d_in[7];
    const float* b_int1 = (const float*)d_in[8];
    const float* W_int2 = (const float*)d_in[9];
    const float* b_int2 = (const float*)d_in[10];
    const float* W_int3 = (const float*)d_in[11];
    const float* b_int3 = (const float*)d_in[12];
    const float* W_int4 = (const float*)d_in[13];
    const float* b_int4 = (const float*)d_in[14];
    const float* W_root = (const float*)d_in[15];
    const float* b_root = (const float*)d_in[16];
    float* out = (float*)d_out;

    float *h1, *h2, *h3, *h4, *h5, *h6, *h7;
    cudaGetSymbolAddress((void**)&h1, g_h1);
    cudaGetSymbolAddress((void**)&h2, g_h2);
    cudaGetSymbolAddress((void**)&h3, g_h3);
    cudaGetSymbolAddress((void**)&h4, g_h4);
    cudaGetSymbolAddress((void**)&h5, g_h5);
    cudaGetSymbolAddress((void**)&h6, g_h6);
    cudaGetSymbolAddress((void**)&h7, g_h7);

    const int TB = TLEN / TT;   // 8 tiles along T
    const long long BSX = (long long)1536 * TLEN;

    const int SM20 = smem_bytes(20, 8);   // ~53 KB -> 3 CTAs/SM
    const int SM16 = smem_bytes(16, 8);   // ~49 KB -> 3 CTAs/SM

    cudaFuncSetAttribute(gconv_kernel<20, 20, 8, true>,
                         cudaFuncAttributeMaxDynamicSharedMemorySize, SM20);
    cudaFuncSetAttribute(gconv_kernel<16, 16, 8, true>,
                         cudaFuncAttributeMaxDynamicSharedMemorySize, SM16);
    cudaFuncSetAttribute(gconv_kernel<16, 8, 8, true>,
                         cudaFuncAttributeMaxDynamicSharedMemorySize, SM16);

    // 1. leaf: 64 groups, 20 in/group, 8 out/group (5 chunks of 4)
    gconv_kernel<20, 20, 8, true><<<dim3(TB, 64, BATCH), NTHREADS, SM20>>>(
        x, BSX, nullptr, 0, W_leaf, b_leaf, h1, 64);

    // 2. int0: 32 groups, 16 in/group (from 512 ch)
    gconv_kernel<16, 16, 8, true><<<dim3(TB, 32, BATCH), NTHREADS, SM16>>>(
        h1, (long long)512 * TLEN, nullptr, 0, W_int0, b_int0, h2, 32);

    // 3. br: 32 groups, in/group = 8 (h2) + 8 (syn = x channels 1280..1535)
    gconv_kernel<16, 8, 8, true><<<dim3(TB, 32, BATCH), NTHREADS, SM16>>>(
        h2, (long long)256 * TLEN,
        x + (long long)1280 * TLEN, BSX,
        W_br, b_br, h3, 32);

    // 4. int1: 16 groups (256 -> 128)
    gconv_kernel<16, 16, 8, true><<<dim3(TB, 16, BATCH), NTHREADS, SM16>>>(
        h3, (long long)256 * TLEN, nullptr, 0, W_int1, b_int1, h4, 16);

    // 5. int2: 8 groups (128 -> 64)
    gconv_kernel<16, 16, 8, true><<<dim3(TB, 8, BATCH), NTHREADS, SM16>>>(
        h4, (long long)128 * TLEN, nullptr, 0, W_int2, b_int2, h5, 8);

    // 6. int3: 4 groups (64 -> 32)
    gconv_kernel<16, 16, 8, true><<<dim3(TB, 4, BATCH), NTHREADS, SM16>>>(
        h5, (long long)64 * TLEN, nullptr, 0, W_int3, b_int3, h6, 4);

    // 7. int4: 2 groups (32 -> 16)
    gconv_kernel<16, 16, 8, true><<<dim3(TB, 2, BATCH), NTHREADS, SM16>>>(
        h6, (long long)32 * TLEN, nullptr, 0, W_int4, b_int4, h7, 2);

    // 8. root: 1x1 conv 16 -> 1
    root_kernel<<<(BATCH * TLEN + 255) / 256, 256>>>(h7, W_root, b_root, out);
}

// round 8
// speedup vs baseline: 1.2914x; 1.0947x over previous
#include <cuda_runtime.h>
#include <cstdint>

// Problem constants
#define BATCH   16
#define TLEN    4096
#define KW      15

// Tiling
#define TT      512     // time tile per CTA
#define TTH     16      // t positions per thread (8 packed adjacent pairs)
#define NTHREADS 256    // 8 warps: (oc-pair = w&3) x (t-half = w>>2)
#define CHUNKI  4       // channels per staged chunk
#define NCHK    132     // 16-B chunks per channel image (pairs 0..263)
#define NRC     34      // chunks per interleave row (33 used + 1 pad col)
#define IMGU    (4*NRC*2)   // u64 per image  = 272
#define CHU     (2*IMGU)    // u64 per channel block (E then O) = 544

typedef unsigned long long u64;

// ---------------------------------------------------------------------------
// Intermediate activation buffers (static device globals; no runtime alloc)
// ---------------------------------------------------------------------------
__device__ float g_h1[(size_t)BATCH * 512 * TLEN];
__device__ float g_h2[(size_t)BATCH * 256 * TLEN];
__device__ float g_h3[(size_t)BATCH * 256 * TLEN];
__device__ float g_h4[(size_t)BATCH * 128 * TLEN];
__device__ float g_h5[(size_t)BATCH *  64 * TLEN];
__device__ float g_h6[(size_t)BATCH *  32 * TLEN];
__device__ float g_h7[(size_t)BATCH *  16 * TLEN];

// ---------------------------------------------------------------------------
// Packed f32x2 helpers (FFMA2 only reachable via PTX)
// ---------------------------------------------------------------------------
__device__ __forceinline__ u64 pack2(float lo, float hi) {
    u64 r; asm("mov.b64 %0,{%1,%2};" : "=l"(r) : "f"(lo), "f"(hi)); return r;
}
__device__ __forceinline__ void unpack2(u64 v, float& lo, float& hi) {
    asm("mov.b64 {%0,%1},%2;" : "=f"(lo), "=f"(hi) : "l"(v));
}
__device__ __forceinline__ u64 ffma2(u64 a, u64 b, u64 c) {
    u64 d; asm("fma.rn.f32x2 %0,%1,%2,%3;" : "=l"(d) : "l"(a), "l"(b), "l"(c));
    return d;
}
__device__ __forceinline__ void cpa16(uint32_t dst, const float* src, int sz) {
    asm volatile("cp.async.cg.shared.global [%0], [%1], 16, %2;\n"
                 :: "r"(dst), "l"(src), "r"(sz));
}
__device__ __forceinline__ void cpa_commit() { asm volatile("cp.async.commit_group;\n"); }
__device__ __forceinline__ void cpa_wait0()  { asm volatile("cp.async.wait_group 0;\n"); }

// ---------------------------------------------------------------------------
// Grouped conv1d K=15 SAME. X2[j] = x[t0-8+j] zero-padded. Pair images:
//   E[i] = (X2[2i],   X2[2i+1])   (serves ODD  taps k=2m-1: acc[a]+=w*E[q+m], m=1..7)
//   O[i] = (X2[2i+1], X2[2i+2])   (serves EVEN taps k=2m  : acc[a]+=w*O[q+m], m=0..7)
// Output pair q = 8Q+a, thread covers t = Q*16..+15, Q = (warp>>2)*16 + (lane&15).
// oc = (warp&3)*2 + (lane>>4)  -> window LDS are 16-addr x 2-broadcast.
// Images stored chunk-interleaved: 16-B chunk c (pairs 2c,2c+1) at row c&3, col c>>2
// -> thread's 8 chunks are at fixed row, consecutive cols => conflict-free LDS.128.
// E staged by 16-B cp.async (edges are whole-chunk in/out: exact zfill);
// O built in smem from E by a tiny conflict-free LDS/STS pass.
// ---------------------------------------------------------------------------
template<int CIN, int C0, int COUT, bool ACT>
__global__ __launch_bounds__(NTHREADS, 3)
void gconv_kernel(const float* __restrict__ in0, long long bs0,
                  const float* __restrict__ in1, long long bs1,
                  const float* __restrict__ W,
                  const float* __restrict__ bias,
                  float* __restrict__ out, int G)
{
    extern __shared__ char smem_raw[];
    u64*   sw2  = (u64*)smem_raw;                    // COUT*CIN*16 SOA weight slots
    u64*   simg = sw2 + COUT * CIN * 16;             // 2 bufs * CHUNKI * CHU
    float* sb   = (float*)(simg + 2 * CHUNKI * CHU);

    const int b   = blockIdx.z;
    const int g   = blockIdx.y;
    const int t0  = blockIdx.x * TT;
    const int tid = threadIdx.x;
    const int warp = tid >> 5, lane = tid & 31;
    const int oc = (warp & 3) * 2 + (lane >> 4);
    const int Q  = (warp >> 2) * 16 + (lane & 15);   // 0..31, t base = Q*16

    // ---- stage SOA packed weights: slot s<8 -> w[2s] (even k); s=8..14 -> w[2(s-8)+1]
    {
        const float* wsrc = W + (long long)g * COUT * CIN * KW;
        for (int i = tid; i < COUT * CIN * 16; i += NTHREADS) {
            int o_ = i / (CIN * 16);
            int r  = i - o_ * (CIN * 16);
            int ci = r >> 4, s = r & 15;
            float w = 0.0f;
            if (s < 8)       w = wsrc[(o_ * CIN + ci) * KW + 2 * s];
            else if (s < 15) w = wsrc[(o_ * CIN + ci) * KW + 2 * (s - 8) + 1];
            sw2[i] = pack2(w, w);
        }
        if (tid < COUT) sb[tid] = bias[g * COUT + tid];
    }

    auto srcbase = [&](int ci) -> const float* {
        if (C0 == CIN || ci < C0)
            return in0 + (long long)b * bs0 + (long long)(g * C0 + ci) * TLEN;
        return in1 + (long long)b * bs1 + (long long)(g * (CIN - C0) + (ci - C0)) * TLEN;
    };

    // stage E images of channels [c0, c0+CHUNKI) into buffer buf via 16-B cp.async
    auto stageE = [&](int c0, int buf) {
        u64* base = simg + buf * (CHUNKI * CHU);
        uint32_t aB = (uint32_t)__cvta_generic_to_shared(base);
        for (int idx = tid; idx < CHUNKI * NCHK; idx += NTHREADS) {
            int cl = idx / NCHK, c = idx - cl * NCHK;
            const float* src = srcbase(c0 + cl);
            int f  = t0 - 8 + 4 * c;                       // multiple of 4
            int sz = ((unsigned)f < (unsigned)(TLEN - 3)) ? 16 : 0;
            int fc = f < 0 ? 0 : (f > TLEN - 4 ? TLEN - 4 : f);
            uint32_t dst = aB + (uint32_t)(cl * CHU * 8)
                              + (uint32_t)((((c & 3) * NRC) + (c >> 2)) * 16);
            cpa16(dst, src + fc, sz);
        }
    };

    // build O images from E (O chunk c floats = X2[4c+1..4c+4])
    auto buildO = [&](int buf) {
        u64* base = simg + buf * (CHUNKI * CHU);
        for (int idx = tid; idx < CHUNKI * NCHK; idx += NTHREADS) {
            int cl = idx / NCHK, c = idx - cl * NCHK;
            float* E = (float*)(base + cl * CHU);
            float* O = E + IMGU * 2;                       // floats
            int p0 = (((c & 3) * NRC) + (c >> 2)) * 4;
            int c1 = c + 1;
            int p1 = ((((c1) & 3) * NRC) + (c1 >> 2)) * 4; // c=131 -> pad col 33
            float4 v = *(float4*)(E + p0);
            float nxt = E[p1];
            *(float4*)(O + p0) = make_float4(v.y, v.z, v.w, nxt);
        }
    };

    u64 acc[8];
#pragma unroll
    for (int j = 0; j < 8; j++) acc[j] = 0ull;

    const u64* wrow = sw2 + oc * CIN * 16;

    // prologue: chunk 0
    stageE(0, 0); cpa_commit(); cpa_wait0();
    __syncthreads();                 // E(0) + weights visible
    buildO(0);
    __syncthreads();

    const int NCH = CIN / CHUNKI;
#pragma unroll 1
    for (int c = 0; c < NCH; c++) {
        const int buf = c & 1;
        if (c + 1 < NCH) stageE((c + 1) * CHUNKI, buf ^ 1);
        cpa_commit();

        u64* bufb = simg + buf * (CHUNKI * CHU);
#pragma unroll 1
        for (int cl = 0; cl < CHUNKI; cl++) {
            const u64* Ei = bufb + cl * CHU + Q * 2;
            const u64* Oi = Ei + IMGU;
            const u64* wp = wrow + (c * CHUNKI + cl) * 16;

            // ---- even-k pass (O image), m = 0..7 ----
            {
                u64 wv[8];
#pragma unroll
                for (int j = 0; j < 4; j++) {
                    ulonglong2 v = ((const ulonglong2*)wp)[j];
                    wv[2*j] = v.x; wv[2*j+1] = v.y;
                }
                u64 o[16];
#pragma unroll
                for (int s = 0; s < 8; s++) {
                    ulonglong2 v = *(const ulonglong2*)(Oi + (s & 3) * (2 * NRC) + (s >> 2) * 2);
                    o[2*s] = v.x; o[2*s+1] = v.y;
                }
#pragma unroll
                for (int m = 0; m < 8; m++) {
#pragma unroll
                    for (int a = 0; a < 8; a++) acc[a] = ffma2(o[a + m], wv[m], acc[a]);
                }
            }
            // ---- odd-k pass (E image), m = 1..7 ----
            {
                u64 wv[8];
#pragma unroll
                for (int j = 0; j < 4; j++) {
                    ulonglong2 v = ((const ulonglong2*)wp)[4 + j];
                    wv[2*j] = v.x; wv[2*j+1] = v.y;
                }
                u64 e[16];
#pragma unroll
                for (int s = 0; s < 8; s++) {
                    ulonglong2 v = *(const ulonglong2*)(Ei + (s & 3) * (2 * NRC) + (s >> 2) * 2);
                    e[2*s] = v.x; e[2*s+1] = v.y;
                }
#pragma unroll
                for (int m = 1; m < 8; m++) {
#pragma unroll
                    for (int a = 0; a < 8; a++) acc[a] = ffma2(e[a + m], wv[m - 1], acc[a]);
                }
            }
        }

        if (c + 1 < NCH) {
            cpa_wait0();
            __syncthreads();         // E(c+1) landed; compute(c) done
            buildO(buf ^ 1);
            __syncthreads();         // O(c+1) visible
        }
    }

    // ---- epilogue: bias + leaky relu, vectorized store ----
    const float bv = sb[oc];
    float res[TTH];
#pragma unroll
    for (int j = 0; j < 8; j++) {
        float lo, hi;
        unpack2(acc[j], lo, hi);
        lo += bv; hi += bv;
        if (ACT) { lo = lo > 0.0f ? lo : 0.01f * lo; hi = hi > 0.0f ? hi : 0.01f * hi; }
        res[2*j] = lo; res[2*j+1] = hi;
    }
    float* dst = out + (((long long)b * G + g) * COUT + oc) * TLEN + t0 + Q * TTH;
#pragma unroll
    for (int j = 0; j < 4; j++)
        ((float4*)dst)[j] = make_float4(res[4*j], res[4*j+1], res[4*j+2], res[4*j+3]);
}

// ---------------------------------------------------------------------------
// Root: 1x1 conv over 16 channels -> 1 channel (no activation)
// ---------------------------------------------------------------------------
__global__ void root_kernel(const float* __restrict__ h,
                            const float* __restrict__ w,
                            const float* __restrict__ bias,
                            float* __restrict__ out)
{
    int idx = blockIdx.x * blockDim.x + threadIdx.x;
    if (idx >= BATCH * TLEN) return;
    int b = idx / TLEN;
    int t = idx - b * TLEN;
    const float* hp = h + (long long)b * 16 * TLEN + t;
    float s = bias[0];
#pragma unroll
    for (int c = 0; c < 16; c++)
        s = fmaf(__ldg(&w[c]), hp[(long long)c * TLEN], s);
    out[idx] = s;
}

// ---------------------------------------------------------------------------
// Launch
// ---------------------------------------------------------------------------
static inline int smem_bytes(int cin, int cout) {
    return cout * cin * 16 * 8            // SOA packed weights
         + 2 * CHUNKI * CHU * 8           // double-buffered E+O chunk images
         + cout * 4;                      // bias
}

extern "C" void kernel_launch(void* const* d_in, const int* in_sizes, int n_in,
                              void* d_out, int out_size)
{
    const float* x      = (const float*)d_in[0];
    const float* W_leaf = (const float*)d_in[1];
    const float* b_leaf = (const float*)d_in[2];
    const float* W_int0 = (const float*)d_in[3];
    const float* b_int0 = (const float*)d_in[4];
    const float* W_br   = (const float*)d_in[5];
    const float* b_br   = (const float*)d_in[6];
    const float* W_int1 = (const float*)d_in[7];
    const float* b_int1 = (const float*)d_in[8];
    const float* W_int2 = (const float*)d_in[9];
    const float* b_int2 = (const float*)d_in[10];
    const float* W_int3 = (const float*)d_in[11];
    const float* b_int3 = (const float*)d_in[12];
    const float* W_int4 = (const float*)d_in[13];
    const float* b_int4 = (const float*)d_in[14];
    const float* W_root = (const float*)d_in[15];
    const float* b_root = (const float*)d_in[16];
    float* out = (float*)d_out;

    float *h1, *h2, *h3, *h4, *h5, *h6, *h7;
    cudaGetSymbolAddress((void**)&h1, g_h1);
    cudaGetSymbolAddress((void**)&h2, g_h2);
    cudaGetSymbolAddress((void**)&h3, g_h3);
    cudaGetSymbolAddress((void**)&h4, g_h4);
    cudaGetSymbolAddress((void**)&h5, g_h5);
    cudaGetSymbolAddress((void**)&h6, g_h6);
    cudaGetSymbolAddress((void**)&h7, g_h7);

    const int TB = TLEN / TT;   // 8 tiles along T
    const long long BSX = (long long)1536 * TLEN;

    const int SM20 = smem_bytes(20, 8);   // ~55 KB -> 3 CTAs/SM
    const int SM16 = smem_bytes(16, 8);   // ~51 KB -> 3 CTAs/SM

    cudaFuncSetAttribute(gconv_kernel<20, 20, 8, true>,
                         cudaFuncAttributeMaxDynamicSharedMemorySize, SM20);
    cudaFuncSetAttribute(gconv_kernel<16, 16, 8, true>,
                         cudaFuncAttributeMaxDynamicSharedMemorySize, SM16);
    cudaFuncSetAttribute(gconv_kernel<16, 8, 8, true>,
                         cudaFuncAttributeMaxDynamicSharedMemorySize, SM16);

    // 1. leaf: 64 groups, 20 in/group, 8 out/group (5 chunks of 4)
    gconv_kernel<20, 20, 8, true><<<dim3(TB, 64, BATCH), NTHREADS, SM20>>>(
        x, BSX, nullptr, 0, W_leaf, b_leaf, h1, 64);

    // 2. int0: 32 groups, 16 in/group (from 512 ch)
    gconv_kernel<16, 16, 8, true><<<dim3(TB, 32, BATCH), NTHREADS, SM16>>>(
        h1, (long long)512 * TLEN, nullptr, 0, W_int0, b_int0, h2, 32);

    // 3. br: 32 groups, in/group = 8 (h2) + 8 (syn = x channels 1280..1535)
    gconv_kernel<16, 8, 8, true><<<dim3(TB, 32, BATCH), NTHREADS, SM16>>>(
        h2, (long long)256 * TLEN,
        x + (long long)1280 * TLEN, BSX,
        W_br, b_br, h3, 32);

    // 4. int1: 16 groups (256 -> 128)
    gconv_kernel<16, 16, 8, true><<<dim3(TB, 16, BATCH), NTHREADS, SM16>>>(
        h3, (long long)256 * TLEN, nullptr, 0, W_int1, b_int1, h4, 16);

    // 5. int2: 8 groups (128 -> 64)
    gconv_kernel<16, 16, 8, true><<<dim3(TB, 8, BATCH), NTHREADS, SM16>>>(
        h4, (long long)128 * TLEN, nullptr, 0, W_int2, b_int2, h5, 8);

    // 6. int3: 4 groups (64 -> 32)
    gconv_kernel<16, 16, 8, true><<<dim3(TB, 4, BATCH), NTHREADS, SM16>>>(
        h5, (long long)64 * TLEN, nullptr, 0, W_int3, b_int3, h6, 4);

    // 7. int4: 2 groups (32 -> 16)
    gconv_kernel<16, 16, 8, true><<<dim3(TB, 2, BATCH), NTHREADS, SM16>>>(
        h6, (long long)32 * TLEN, nullptr, 0, W_int4, b_int4, h7, 2);

    // 8. root: 1x1 conv 16 -> 1
    root_kernel<<<(BATCH * TLEN + 255) / 256, 256>>>(h7, W_root, b_root, out);
}